// round 1
// baseline (speedup 1.0000x reference)
#include <cuda_runtime.h>
#include <cstdint>

// Problem constants
#define BB 4
#define SS 1024
#define DD 512
#define HH 8
#define DKK 64
#define BSD (BB*SS*DD)   // 2097152

// ---------------- scratch (device globals; no allocation) ----------------
__device__ float g_bufQ[2][BSD];
__device__ float g_bufK[2][BSD];
__device__ float g_bufV[2][BSD];
__device__ float g_bufO[2][BSD];

__device__ __forceinline__ float* buf_by_sel(int sel) {
    switch (sel) {
        case 0: return g_bufQ[0];
        case 1: return g_bufK[0];
        case 2: return g_bufV[0];
        case 3: return g_bufQ[1];
        case 4: return g_bufK[1];
        case 5: return g_bufV[1];
        case 6: return g_bufO[0];
        default: return g_bufO[1];
    }
}

// ---------------- GEMM: C[M,N] = A[M,K] @ W[K,N] + bias[N] ----------------
// 64x64 tile, BK=16, 256 threads, 4x4 per-thread register blocking.
#define GBM 64
#define GBN 64
#define GBK 16

__global__ void gemm_bias_kernel(const float* __restrict__ A, int asel,
                                 const float* __restrict__ W,
                                 const float* __restrict__ bias,
                                 float* __restrict__ C, int csel,
                                 int M, int N, int K) {
    if (A == nullptr) A = buf_by_sel(asel);
    if (C == nullptr) C = buf_by_sel(csel);

    __shared__ float As[GBM][GBK + 1];
    __shared__ float Ws[GBK][GBN];

    const int tid = threadIdx.x;
    const int tx = tid & 15;        // 0..15
    const int ty = tid >> 4;        // 0..15
    const int m0 = blockIdx.y * GBM;
    const int n0 = blockIdx.x * GBN;

    float acc[4][4] = {};

    for (int k0 = 0; k0 < K; k0 += GBK) {
        #pragma unroll
        for (int r = 0; r < 4; r++) {
            int idx = tid + r * 256;            // 0..1023
            int m = idx >> 4;                   // /16
            int k = idx & 15;
            As[m][k] = A[(size_t)(m0 + m) * K + k0 + k];
        }
        #pragma unroll
        for (int r = 0; r < 4; r++) {
            int idx = tid + r * 256;
            int k = idx >> 6;                   // /64
            int n = idx & 63;
            Ws[k][n] = W[(size_t)(k0 + k) * N + n0 + n];
        }
        __syncthreads();

        #pragma unroll
        for (int k = 0; k < GBK; k++) {
            float a[4], w[4];
            #pragma unroll
            for (int i = 0; i < 4; i++) a[i] = As[ty * 4 + i][k];
            #pragma unroll
            for (int j = 0; j < 4; j++) w[j] = Ws[k][tx * 4 + j];
            #pragma unroll
            for (int i = 0; i < 4; i++)
                #pragma unroll
                for (int j = 0; j < 4; j++)
                    acc[i][j] += a[i] * w[j];
        }
        __syncthreads();
    }

    #pragma unroll
    for (int i = 0; i < 4; i++) {
        int m = m0 + ty * 4 + i;
        #pragma unroll
        for (int j = 0; j < 4; j++) {
            int n = n0 + tx * 4 + j;
            C[(size_t)m * N + n] = acc[i][j] + bias[n];
        }
    }
}

// ---------------- attention: one block per (q, b*h, stream) ----------------
__device__ __forceinline__ float warpReduceSum(float v) {
    #pragma unroll
    for (int o = 16; o > 0; o >>= 1) v += __shfl_xor_sync(0xffffffffu, v, o);
    return v;
}
__device__ __forceinline__ float warpReduceMax(float v) {
    #pragma unroll
    for (int o = 16; o > 0; o >>= 1) v = fmaxf(v, __shfl_xor_sync(0xffffffffu, v, o));
    return v;
}

__global__ __launch_bounds__(256)
void attn_kernel(const float* __restrict__ gammas) {
    const int q  = blockIdx.x;
    const int bh = blockIdx.y;
    const int b  = bh >> 3;
    const int h  = bh & 7;
    const int st = blockIdx.z;

    const int tid  = threadIdx.x;
    const int lane = tid & 31;
    const int w    = tid >> 5;          // warp id 0..7
    const int L    = q + 1;             // causal: keys 0..q valid

    const float* __restrict__ Qp    = g_bufQ[st] + (size_t)(b * SS + q) * DD + h * DKK;
    const float* __restrict__ Kbase = g_bufK[st] + (size_t)(b * SS) * DD + h * DKK;
    const float* __restrict__ Vbase = g_bufV[st] + (size_t)(b * SS) * DD + h * DKK;

    __shared__ float s_sc[SS];          // raw scaled scores
    __shared__ float s_p[SS];           // exp / cumsum / a (reused)
    __shared__ float s_q[DKK];
    __shared__ float s_wred[8];
    __shared__ float s_bc;
    __shared__ float s_opart[8][DKK];

    if (tid < DKK) s_q[tid] = Qp[tid];
    __syncthreads();
    const float q0 = s_q[lane];
    const float q1 = s_q[lane + 32];

    // ---- scores: warp per key, lanes over DK ----
    for (int j = w; j < L; j += 8) {
        const float* kr = Kbase + (size_t)j * DD;
        float v = q0 * kr[lane] + q1 * kr[lane + 32];
        v = warpReduceSum(v);
        if (lane == 0) s_sc[j] = v * 0.125f;    // 1/sqrt(64)
    }
    __syncthreads();

    // ---- softmax #1 (unnormalized exps; zero beyond L) ----
    float m = -3.0e38f;
    for (int j = tid; j < L; j += 256) m = fmaxf(m, s_sc[j]);
    m = warpReduceMax(m);
    if (lane == 0) s_wred[w] = m;
    __syncthreads();
    if (tid == 0) {
        float mm = s_wred[0];
        #pragma unroll
        for (int i = 1; i < 8; i++) mm = fmaxf(mm, s_wred[i]);
        s_bc = mm;
    }
    __syncthreads();
    const float rmax1 = s_bc;
    for (int j = tid; j < SS; j += 256)
        s_p[j] = (j < L) ? __expf(s_sc[j] - rmax1) : 0.0f;
    __syncthreads();

    // ---- inclusive cumsum of s_p[0..SS) ----
    const int base = tid * 4;
    float v4[4];
    v4[0] = s_p[base];
    v4[1] = v4[0] + s_p[base + 1];
    v4[2] = v4[1] + s_p[base + 2];
    v4[3] = v4[2] + s_p[base + 3];
    float tsum = v4[3];
    float inc = tsum;
    #pragma unroll
    for (int d = 1; d < 32; d <<= 1) {
        float y = __shfl_up_sync(0xffffffffu, inc, d);
        if (lane >= d) inc += y;
    }
    if (lane == 31) s_wred[w] = inc;
    __syncthreads();
    if (tid == 0) {
        float run = 0.f;
        #pragma unroll
        for (int i = 0; i < 8; i++) { run += s_wred[i]; s_wred[i] = run; }
    }
    __syncthreads();
    const float warp_excl = (w > 0) ? s_wred[w - 1] : 0.0f;
    const float tot = s_wred[7];
    const float texcl = warp_excl + inc - tsum;
    s_p[base]     = texcl + v4[0];
    s_p[base + 1] = texcl + v4[1];
    s_p[base + 2] = texcl + v4[2];
    s_p[base + 3] = texcl + v4[3];
    __syncthreads();

    // ---- distance decay + rescaled scores ----
    const float gh = gammas[h];
    const float gv = -log1pf(__expf(gh));     // -softplus(gamma)
    const float rtot = 1.0f / tot;
    for (int j = tid; j < L; j += 256) {
        float rem = fmaxf((tot - s_p[j]) * rtot, 0.0f);
        float pos = (float)(q - j);
        float dist = sqrtf(fmaxf(rem * pos, 0.0f));
        float em = __expf(dist * gv);
        em = fminf(fmaxf(em, 1e-5f), 1e5f);
        s_p[j] = s_sc[j] * em;
    }
    __syncthreads();

    // ---- softmax #2 ----
    m = -3.0e38f;
    for (int j = tid; j < L; j += 256) m = fmaxf(m, s_p[j]);
    m = warpReduceMax(m);
    if (lane == 0) s_wred[w] = m;
    __syncthreads();
    if (tid == 0) {
        float mm = s_wred[0];
        #pragma unroll
        for (int i = 1; i < 8; i++) mm = fmaxf(mm, s_wred[i]);
        s_bc = mm;
    }
    __syncthreads();
    const float rmax2 = s_bc;
    float psum = 0.0f;
    for (int j = tid; j < L; j += 256) {
        float e = __expf(s_p[j] - rmax2);
        s_p[j] = e;
        psum += e;
    }
    psum = warpReduceSum(psum);
    if (lane == 0) s_wred[w] = psum;
    __syncthreads();
    if (tid == 0) {
        float ss = 0.f;
        #pragma unroll
        for (int i = 0; i < 8; i++) ss += s_wred[i];
        s_bc = ss;
    }
    __syncthreads();
    const float rsum = 1.0f / s_bc;

    // ---- output: o[d] = sum_j a_j * V[j][d] ----
    float a0 = 0.f, a1 = 0.f;
    for (int j = w; j < L; j += 8) {
        const float* vr = Vbase + (size_t)j * DD;
        float a = s_p[j];
        a0 += a * vr[lane];
        a1 += a * vr[lane + 32];
    }
    s_opart[w][lane]      = a0;
    s_opart[w][lane + 32] = a1;
    __syncthreads();
    if (tid < DKK) {
        float o = 0.f;
        #pragma unroll
        for (int i = 0; i < 8; i++) o += s_opart[i][tid];
        g_bufO[st][(size_t)(b * SS + q) * DD + h * DKK + tid] = o * rsum;
    }
}

// ---------------- launch ----------------
extern "C" void kernel_launch(void* const* d_in, const int* in_sizes, int n_in,
                              void* d_out, int out_size) {
    const float* q_m  = (const float*)d_in[0];
    const float* q_c  = (const float*)d_in[1];
    const float* k_m  = (const float*)d_in[2];
    const float* k_c  = (const float*)d_in[3];
    const float* v_m  = (const float*)d_in[4];
    const float* v_c  = (const float*)d_in[5];
    const float* Wk_m = (const float*)d_in[6];
    const float* bk_m = (const float*)d_in[7];
    const float* Wk_c = (const float*)d_in[8];
    const float* bk_c = (const float*)d_in[9];
    const float* Wv_m = (const float*)d_in[10];
    const float* bv_m = (const float*)d_in[11];
    const float* Wv_c = (const float*)d_in[12];
    const float* bv_c = (const float*)d_in[13];
    const float* Wo_m = (const float*)d_in[14];
    const float* bo_m = (const float*)d_in[15];
    const float* Wo_c = (const float*)d_in[16];
    const float* bo_c = (const float*)d_in[17];
    const float* gam  = (const float*)d_in[18];
    float* out = (float*)d_out;

    const int M = BB * SS;   // 4096
    dim3 ggrid(DD / GBN, M / GBM);   // (8, 64)

    // projections (Q and K share Wk per stream)
    gemm_bias_kernel<<<ggrid, 256>>>(q_m, 0, Wk_m, bk_m, nullptr, 0, M, DD, DD);
    gemm_bias_kernel<<<ggrid, 256>>>(k_m, 0, Wk_m, bk_m, nullptr, 1, M, DD, DD);
    gemm_bias_kernel<<<ggrid, 256>>>(v_m, 0, Wv_m, bv_m, nullptr, 2, M, DD, DD);
    gemm_bias_kernel<<<ggrid, 256>>>(q_c, 0, Wk_c, bk_c, nullptr, 3, M, DD, DD);
    gemm_bias_kernel<<<ggrid, 256>>>(k_c, 0, Wk_c, bk_c, nullptr, 4, M, DD, DD);
    gemm_bias_kernel<<<ggrid, 256>>>(v_c, 0, Wv_c, bv_c, nullptr, 5, M, DD, DD);

    // attention (both streams)
    dim3 agrid(SS, BB * HH, 2);
    attn_kernel<<<agrid, 256>>>(gam);

    // output projections
    gemm_bias_kernel<<<ggrid, 256>>>(nullptr, 6, Wo_m, bo_m, out, 0, M, DD, DD);
    gemm_bias_kernel<<<ggrid, 256>>>(nullptr, 7, Wo_c, bo_c, out + BSD, 0, M, DD, DD);
}

// round 2
// speedup vs baseline: 1.5115x; 1.5115x over previous
#include <cuda_runtime.h>
#include <cstdint>

// Problem constants
#define BB 4
#define SS 1024
#define DD 512
#define HH 8
#define DKK 64
#define BSD (BB*SS*DD)   // 2097152
#define TQ 8             // query rows per attention CTA

// ---------------- scratch (device globals; no allocation) ----------------
__device__ float g_bufQ[2][BSD];
__device__ float g_bufK[2][BSD];
__device__ float g_bufV[2][BSD];
__device__ float g_bufO[2][BSD];

// ---------------- batched GEMM: C = A[4096,512] @ W[512,512] + bias ----------------
struct GB  { const float* A; const float* W; const float* bias; float* C; };
struct GB8 { GB g[8]; };

#define GM 64
#define GN 64
#define GK 16

__global__ __launch_bounds__(256)
void gemm_batch_kernel(GB8 args) {
    const GB p = args.g[blockIdx.z];

    __shared__ __align__(16) float As[GK][68];   // k-major, padded
    __shared__ __align__(16) float Ws[GK][GN];

    const int tid = threadIdx.x;
    const int tx = tid & 15;         // 0..15 (n)
    const int ty = tid >> 4;         // 0..15 (m)
    const int m0 = blockIdx.y * GM;
    const int n0 = blockIdx.x * GN;

    // load indices
    const int lm = tid >> 2;         // 0..63 (A row)
    const int lkq = tid & 3;         // 0..3  (A k-quad)
    const int lk = tid >> 4;         // 0..15 (W row)
    const int lnq = tid & 15;        // 0..15 (W n-quad)

    float acc[4][4] = {};

    for (int k0 = 0; k0 < 512; k0 += GK) {
        // A tile 64x16 -> As[k][m] (scatter)
        float4 a4 = *(const float4*)(p.A + (size_t)(m0 + lm) * 512 + k0 + lkq * 4);
        As[lkq * 4 + 0][lm] = a4.x;
        As[lkq * 4 + 1][lm] = a4.y;
        As[lkq * 4 + 2][lm] = a4.z;
        As[lkq * 4 + 3][lm] = a4.w;
        // W tile 16x64 -> Ws[k][n]
        *(float4*)&Ws[lk][lnq * 4] =
            *(const float4*)(p.W + (size_t)(k0 + lk) * 512 + n0 + lnq * 4);
        __syncthreads();

        #pragma unroll
        for (int k = 0; k < GK; k++) {
            float4 av = *(const float4*)&As[k][ty * 4];
            float4 wv = *(const float4*)&Ws[k][tx * 4];
            acc[0][0] += av.x * wv.x; acc[0][1] += av.x * wv.y;
            acc[0][2] += av.x * wv.z; acc[0][3] += av.x * wv.w;
            acc[1][0] += av.y * wv.x; acc[1][1] += av.y * wv.y;
            acc[1][2] += av.y * wv.z; acc[1][3] += av.y * wv.w;
            acc[2][0] += av.z * wv.x; acc[2][1] += av.z * wv.y;
            acc[2][2] += av.z * wv.z; acc[2][3] += av.z * wv.w;
            acc[3][0] += av.w * wv.x; acc[3][1] += av.w * wv.y;
            acc[3][2] += av.w * wv.z; acc[3][3] += av.w * wv.w;
        }
        __syncthreads();
    }

    float4 b4 = *(const float4*)(p.bias + n0 + tx * 4);
    #pragma unroll
    for (int i = 0; i < 4; i++) {
        float4 o;
        o.x = acc[i][0] + b4.x;
        o.y = acc[i][1] + b4.y;
        o.z = acc[i][2] + b4.z;
        o.w = acc[i][3] + b4.w;
        *(float4*)(p.C + (size_t)(m0 + ty * 4 + i) * 512 + n0 + tx * 4) = o;
    }
}

// ---------------- attention: one CTA per (q-tile of 8, b*h, stream) ----------------
__device__ __forceinline__ float warpReduceSum(float v) {
    #pragma unroll
    for (int o = 16; o > 0; o >>= 1) v += __shfl_xor_sync(0xffffffffu, v, o);
    return v;
}
__device__ __forceinline__ float warpReduceMax(float v) {
    #pragma unroll
    for (int o = 16; o > 0; o >>= 1) v = fmaxf(v, __shfl_xor_sync(0xffffffffu, v, o));
    return v;
}

__global__ __launch_bounds__(256)
void attn_kernel(const float* __restrict__ gammas) {
    const int q0 = blockIdx.x * TQ;
    const int bh = blockIdx.y;
    const int b  = bh >> 3;
    const int h  = bh & 7;
    const int st = blockIdx.z;

    const int tid  = threadIdx.x;
    const int lane = tid & 31;
    const int w    = tid >> 5;       // warp id 0..7 == local query row

    const float* __restrict__ Qbase = g_bufQ[st] + ((size_t)(b * SS + q0)) * DD + h * DKK;
    const float* __restrict__ Kbase = g_bufK[st] + (size_t)b * SS * DD + h * DKK;
    const float* __restrict__ Vbase = g_bufV[st] + (size_t)b * SS * DD + h * DKK;

    __shared__ __align__(16) float s_sc[TQ][SS];     // scores -> probs (32 KB)
    __shared__ __align__(16) float s_q[TQ][DKK];     // Q tile
    __shared__ __align__(16) float s_kv[32][68];     // K/V chunk (padded)

    // load Q tile (8x64)
    if (tid < 128) {
        int r = tid >> 4, dq = tid & 15;
        *(float4*)&s_q[r][dq * 4] = *(const float4*)(Qbase + (size_t)r * DD + dq * 4);
    }

    const int Lmax = q0 + TQ;
    const int nch  = (Lmax + 31) >> 5;

    // ---------- Phase 1: scores ----------
    for (int c = 0; c < nch; c++) {
        #pragma unroll
        for (int r = 0; r < 2; r++) {
            int f = tid + r * 256;             // 0..511
            int j = f >> 4, dq = f & 15;
            *(float4*)&s_kv[j][dq * 4] =
                *(const float4*)(Kbase + (size_t)(c * 32 + j) * DD + dq * 4);
        }
        __syncthreads();
        float acc = 0.f;
        #pragma unroll
        for (int dq = 0; dq < 16; dq++) {
            float4 k4 = *(const float4*)&s_kv[lane][dq * 4];
            float4 q4 = *(const float4*)&s_q[w][dq * 4];
            acc += k4.x * q4.x + k4.y * q4.y + k4.z * q4.z + k4.w * q4.w;
        }
        s_sc[w][c * 32 + lane] = acc * 0.125f;   // 1/sqrt(64)
        __syncthreads();
    }

    // ---------- Phase 2: per-row softmax / cumsum / decay / softmax (warp-local) ----------
    float* row = s_sc[w];
    const int rl = q0 + w;       // global query index
    const int Lr = rl + 1;       // valid keys

    // max of raw scores
    float m1 = -3.0e38f;
    #pragma unroll
    for (int i = 0; i < 32; i++) {
        int j = i * 32 + lane;
        if (j < Lr) m1 = fmaxf(m1, row[j]);
    }
    m1 = warpReduceMax(m1);

    // exp + inclusive cumsum (carry-chain warp scans, interleaved ownership)
    float c_reg[32];
    float tot;
    {
        float carry = 0.f;
        #pragma unroll
        for (int i = 0; i < 32; i++) {
            int j = i * 32 + lane;
            float e = (j < Lr) ? __expf(row[j] - m1) : 0.f;
            float x = e;
            #pragma unroll
            for (int d = 1; d < 32; d <<= 1) {
                float y = __shfl_up_sync(0xffffffffu, x, d);
                if (lane >= d) x += y;
            }
            c_reg[i] = carry + x;
            carry += __shfl_sync(0xffffffffu, x, 31);
        }
        tot = carry;
    }

    const float gh = gammas[h];
    const float gv = -log1pf(__expf(gh));      // -softplus(gamma)
    const float rtot = 1.0f / tot;

    // distance decay + rescale, track new max
    float m2 = -3.0e38f;
    #pragma unroll
    for (int i = 0; i < 32; i++) {
        int j = i * 32 + lane;
        if (j < Lr) {
            float s = row[j];
            float rem = fmaxf((tot - c_reg[i]) * rtot, 0.f);
            float dist = sqrtf(rem * (float)(rl - j));
            float em = fminf(fmaxf(__expf(dist * gv), 1e-5f), 1e5f);
            float v = s * em;
            row[j] = v;
            m2 = fmaxf(m2, v);
        }
    }
    m2 = warpReduceMax(m2);

    // softmax #2 (unnormalized; fold 1/sum into epilogue)
    float psum = 0.f;
    #pragma unroll
    for (int i = 0; i < 32; i++) {
        int j = i * 32 + lane;
        if (j < Lr) {
            float e = __expf(row[j] - m2);
            row[j] = e;
            psum += e;
        }
    }
    psum = warpReduceSum(psum);
    const float rsum = 1.0f / psum;

    // ---------- Phase 3: O = P @ V ----------
    float acc0 = 0.f, acc1 = 0.f;
    const int d0 = lane * 2;
    for (int c = 0; c < nch; c++) {
        #pragma unroll
        for (int r = 0; r < 2; r++) {
            int f = tid + r * 256;
            int j = f >> 4, dq = f & 15;
            *(float4*)&s_kv[j][dq * 4] =
                *(const float4*)(Vbase + (size_t)(c * 32 + j) * DD + dq * 4);
        }
        __syncthreads();
        const int cbase = c * 32;
        #pragma unroll
        for (int jq = 0; jq < 8; jq++) {
            int gj = cbase + jq * 4;
            if (gj < Lr) {
                float4 p4 = *(const float4*)&s_sc[w][gj];
                float pv[4] = {p4.x, p4.y, p4.z, p4.w};
                #pragma unroll
                for (int u = 0; u < 4; u++) {
                    if (gj + u < Lr) {
                        float2 v2 = *(const float2*)&s_kv[jq * 4 + u][d0];
                        acc0 += pv[u] * v2.x;
                        acc1 += pv[u] * v2.y;
                    }
                }
            }
        }
        __syncthreads();
    }

    float2 o2;
    o2.x = acc0 * rsum;
    o2.y = acc1 * rsum;
    *(float2*)(g_bufO[st] + ((size_t)(b * SS + rl)) * DD + h * DKK + d0) = o2;
}

// ---------------- launch ----------------
extern "C" void kernel_launch(void* const* d_in, const int* in_sizes, int n_in,
                              void* d_out, int out_size) {
    const float* q_m  = (const float*)d_in[0];
    const float* q_c  = (const float*)d_in[1];
    const float* k_m  = (const float*)d_in[2];
    const float* k_c  = (const float*)d_in[3];
    const float* v_m  = (const float*)d_in[4];
    const float* v_c  = (const float*)d_in[5];
    const float* Wk_m = (const float*)d_in[6];
    const float* bk_m = (const float*)d_in[7];
    const float* Wk_c = (const float*)d_in[8];
    const float* bk_c = (const float*)d_in[9];
    const float* Wv_m = (const float*)d_in[10];
    const float* bv_m = (const float*)d_in[11];
    const float* Wv_c = (const float*)d_in[12];
    const float* bv_c = (const float*)d_in[13];
    const float* Wo_m = (const float*)d_in[14];
    const float* bo_m = (const float*)d_in[15];
    const float* Wo_c = (const float*)d_in[16];
    const float* bo_c = (const float*)d_in[17];
    const float* gam  = (const float*)d_in[18];
    float* out = (float*)d_out;

    float *bQ, *bK, *bV, *bO;
    cudaGetSymbolAddress((void**)&bQ, g_bufQ);
    cudaGetSymbolAddress((void**)&bK, g_bufK);
    cudaGetSymbolAddress((void**)&bV, g_bufV);
    cudaGetSymbolAddress((void**)&bO, g_bufO);

    // 6 projection GEMMs in one launch (Q and K share Wk per stream)
    GB8 proj{};
    proj.g[0] = { q_m, Wk_m, bk_m, bQ };
    proj.g[1] = { k_m, Wk_m, bk_m, bK };
    proj.g[2] = { v_m, Wv_m, bv_m, bV };
    proj.g[3] = { q_c, Wk_c, bk_c, bQ + BSD };
    proj.g[4] = { k_c, Wk_c, bk_c, bK + BSD };
    proj.g[5] = { v_c, Wv_c, bv_c, bV + BSD };
    gemm_batch_kernel<<<dim3(512 / GN, 4096 / GM, 6), 256>>>(proj);

    // attention (both streams)
    attn_kernel<<<dim3(SS / TQ, BB * HH, 2), 256>>>(gam);

    // 2 output GEMMs in one launch
    GB8 outp{};
    outp.g[0] = { bO,       Wo_m, bo_m, out };
    outp.g[1] = { bO + BSD, Wo_c, bo_c, out + BSD };
    gemm_batch_kernel<<<dim3(512 / GN, 4096 / GM, 2), 256>>>(outp);
}

// round 3
// speedup vs baseline: 2.1327x; 1.4110x over previous
#include <cuda_runtime.h>
#include <cstdint>

// Problem constants
#define BB 4
#define SS 1024
#define DD 512
#define HH 8
#define DKK 64
#define BSD (BB*SS*DD)   // 2097152
#define TQ 8             // query rows per attention CTA
#define CK 128           // keys per attention chunk

// ---------------- scratch (device globals; no allocation) ----------------
__device__ float g_bufQ[2][BSD];
__device__ float g_bufK[2][BSD];
__device__ float g_bufV[2][BSD];
__device__ float g_bufO[2][BSD];

// ---------------- batched GEMM: C = A[4096,512] @ W[512,512] + bias ----------------
struct GB  { const float* A; const float* W; const float* bias; float* C; };
struct GB8 { GB g[8]; };

#define GM 64
#define GN 64
#define GK 16

__global__ __launch_bounds__(256)
void gemm_batch_kernel(GB8 args) {
    const GB p = args.g[blockIdx.z];

    __shared__ __align__(16) float As[2][GK][68];   // k-major, padded
    __shared__ __align__(16) float Ws[2][GK][GN];

    const int tid = threadIdx.x;
    const int tx = tid & 15;         // n quad
    const int ty = tid >> 4;         // m quad
    const int m0 = blockIdx.y * GM;
    const int n0 = blockIdx.x * GN;

    const int lm  = tid >> 2;        // A row 0..63
    const int lkq = tid & 3;         // A k-quad 0..3
    const int lk  = tid >> 4;        // W row 0..15
    const int lnq = tid & 15;        // W n-quad

    const float* Aptr = p.A + (size_t)(m0 + lm) * 512 + lkq * 4;
    const float* Wptr = p.W + (size_t)lk * 512 + n0 + lnq * 4;

    float4 a4 = *(const float4*)(Aptr);
    float4 w4 = *(const float4*)(Wptr);
    As[0][lkq * 4 + 0][lm] = a4.x;
    As[0][lkq * 4 + 1][lm] = a4.y;
    As[0][lkq * 4 + 2][lm] = a4.z;
    As[0][lkq * 4 + 3][lm] = a4.w;
    *(float4*)&Ws[0][lk][lnq * 4] = w4;
    __syncthreads();

    float acc[4][4] = {};
    int buf = 0;

    for (int k0 = 0; k0 < 512; k0 += GK) {
        const bool more = (k0 + GK) < 512;
        if (more) {
            a4 = *(const float4*)(Aptr + k0 + GK);
            w4 = *(const float4*)(Wptr + (size_t)(k0 + GK) * 512);
        }
        #pragma unroll
        for (int k = 0; k < GK; k++) {
            float4 av = *(const float4*)&As[buf][k][ty * 4];
            float4 wv = *(const float4*)&Ws[buf][k][tx * 4];
            acc[0][0] += av.x * wv.x; acc[0][1] += av.x * wv.y;
            acc[0][2] += av.x * wv.z; acc[0][3] += av.x * wv.w;
            acc[1][0] += av.y * wv.x; acc[1][1] += av.y * wv.y;
            acc[1][2] += av.y * wv.z; acc[1][3] += av.y * wv.w;
            acc[2][0] += av.z * wv.x; acc[2][1] += av.z * wv.y;
            acc[2][2] += av.z * wv.z; acc[2][3] += av.z * wv.w;
            acc[3][0] += av.w * wv.x; acc[3][1] += av.w * wv.y;
            acc[3][2] += av.w * wv.z; acc[3][3] += av.w * wv.w;
        }
        if (more) {
            int nb = buf ^ 1;
            As[nb][lkq * 4 + 0][lm] = a4.x;
            As[nb][lkq * 4 + 1][lm] = a4.y;
            As[nb][lkq * 4 + 2][lm] = a4.z;
            As[nb][lkq * 4 + 3][lm] = a4.w;
            *(float4*)&Ws[nb][lk][lnq * 4] = w4;
        }
        __syncthreads();
        buf ^= 1;
    }

    float4 b4 = *(const float4*)(p.bias + n0 + tx * 4);
    #pragma unroll
    for (int i = 0; i < 4; i++) {
        float4 o;
        o.x = acc[i][0] + b4.x;
        o.y = acc[i][1] + b4.y;
        o.z = acc[i][2] + b4.z;
        o.w = acc[i][3] + b4.w;
        *(float4*)(p.C + (size_t)(m0 + ty * 4 + i) * 512 + n0 + tx * 4) = o;
    }
}

// ---------------- attention ----------------
__device__ __forceinline__ float warpReduceSum(float v) {
    #pragma unroll
    for (int o = 16; o > 0; o >>= 1) v += __shfl_xor_sync(0xffffffffu, v, o);
    return v;
}
__device__ __forceinline__ float warpReduceMax(float v) {
    #pragma unroll
    for (int o = 16; o > 0; o >>= 1) v = fmaxf(v, __shfl_xor_sync(0xffffffffu, v, o));
    return v;
}

// dynamic smem layout (floats):
//   s_sc   [8][1024]       8192
//   s_q    [8][64]          512
//   s_kv   [128][68]       8704
//   s_part [8][8][64]      4096
//   s_rsum [8]                8
#define SMEM_ATTN_FLOATS (8192 + 512 + 8704 + 4096 + 8)

__global__ __launch_bounds__(256)
void attn_kernel(const float* __restrict__ gammas) {
    extern __shared__ float sm[];
    float* s_sc   = sm;               // [r*1024 + j]
    float* s_q    = sm + 8192;        // [r*64 + d]
    float* s_kv   = sm + 8704;        // [j*68 + d]
    float* s_part = sm + 17408;       // [(s*8 + r)*64 + d]
    float* s_rsum = sm + 21504;

    const int q0 = blockIdx.x * TQ;
    const int bh = blockIdx.y;
    const int b  = bh >> 3;
    const int h  = bh & 7;
    const int st = blockIdx.z;

    const int tid  = threadIdx.x;
    const int lane = tid & 31;
    const int w    = tid >> 5;          // warp 0..7

    const float* __restrict__ Qbase = g_bufQ[st] + ((size_t)(b * SS + q0)) * DD + h * DKK;
    const float* __restrict__ Kbase = g_bufK[st] + (size_t)b * SS * DD + h * DKK;
    const float* __restrict__ Vbase = g_bufV[st] + (size_t)b * SS * DD + h * DKK;

    // load Q tile (8x64)
    if (tid < 128) {
        int r = tid >> 4, dq = tid & 15;
        *(float4*)&s_q[r * 64 + dq * 4] = *(const float4*)(Qbase + (size_t)r * DD + dq * 4);
    }

    const int Lmax = q0 + TQ;
    const int nch  = (Lmax + CK - 1) / CK;

    // chunk-load thread mapping (coalesced, conflict-free STS)
    const int ldq = tid & 15;            // dk quad
    const int ljj = tid >> 4;            // key sub-row 0..15

    // ---------- Phase 1: scores ----------
    const int kg = w & 3;                // key group within chunk (32 keys)
    const int rh = (w >> 2) * 4;         // row half (rows rh..rh+3)

    for (int c = 0; c < nch; c++) {
        #pragma unroll
        for (int jt = 0; jt < 8; jt++) {
            int j = ljj + jt * 16;
            *(float4*)&s_kv[j * 68 + ldq * 4] =
                *(const float4*)(Kbase + (size_t)(c * CK + j) * DD + ldq * 4);
        }
        __syncthreads();

        const int jbase = c * CK + kg * 32;
        if (jbase < Lmax) {
            const float* kp = &s_kv[(kg * 32 + lane) * 68];
            float acc[4] = {};
            #pragma unroll
            for (int dq = 0; dq < 16; dq++) {
                float4 k4 = *(const float4*)(kp + dq * 4);
                #pragma unroll
                for (int r = 0; r < 4; r++) {
                    float4 q4 = *(const float4*)&s_q[(rh + r) * 64 + dq * 4];
                    acc[r] += k4.x * q4.x + k4.y * q4.y + k4.z * q4.z + k4.w * q4.w;
                }
            }
            #pragma unroll
            for (int r = 0; r < 4; r++)
                s_sc[(rh + r) * 1024 + jbase + lane] = acc[r] * 0.125f;
        }
        __syncthreads();
    }

    // ---------- Phase 2: per-row softmax / cumsum / decay / softmax ----------
    {
        float* row = s_sc + w * 1024;
        const int rl = q0 + w;
        const int Lr = rl + 1;

        float m1 = -3.0e38f;
        #pragma unroll
        for (int i = 0; i < 32; i++) {
            int j = i * 32 + lane;
            if (j < Lr) m1 = fmaxf(m1, row[j]);
        }
        m1 = warpReduceMax(m1);

        float c_reg[32];
        float tot;
        {
            float carry = 0.f;
            #pragma unroll
            for (int i = 0; i < 32; i++) {
                int j = i * 32 + lane;
                float x = (j < Lr) ? __expf(row[j] - m1) : 0.f;
                #pragma unroll
                for (int d = 1; d < 32; d <<= 1) {
                    float y = __shfl_up_sync(0xffffffffu, x, d);
                    if (lane >= d) x += y;
                }
                c_reg[i] = carry + x;
                carry += __shfl_sync(0xffffffffu, x, 31);
            }
            tot = carry;
        }

        const float gh = gammas[h];
        const float gv = -log1pf(__expf(gh));
        const float rtot = 1.0f / tot;

        float m2 = -3.0e38f;
        #pragma unroll
        for (int i = 0; i < 32; i++) {
            int j = i * 32 + lane;
            if (j < Lr) {
                float s = row[j];
                float rem = fmaxf((tot - c_reg[i]) * rtot, 0.f);
                float dist = sqrtf(rem * (float)(rl - j));
                float em = fminf(fmaxf(__expf(dist * gv), 1e-5f), 1e5f);
                float v = s * em;
                row[j] = v;
                m2 = fmaxf(m2, v);
            }
        }
        m2 = warpReduceMax(m2);

        float psum = 0.f;
        #pragma unroll
        for (int i = 0; i < 32; i++) {
            int j = i * 32 + lane;
            float e = 0.f;
            if (j < Lr) {
                e = __expf(row[j] - m2);
                psum += e;
            }
            row[j] = e;                 // zero beyond Lr for phase 3
        }
        psum = warpReduceSum(psum);
        if (lane == 0) s_rsum[w] = 1.0f / psum;
    }
    __syncthreads();

    // ---------- Phase 3: O = P @ V ----------
    // warp w = key segment of 16 within chunk; lane = (rg, dkq)
    const int rg  = lane >> 4;           // row group 0/1 (rows rg*4..rg*4+3)
    const int dkq = lane & 15;           // dk quad

    float4 acc4[4] = {};
    for (int c = 0; c < nch; c++) {
        #pragma unroll
        for (int jt = 0; jt < 8; jt++) {
            int j = ljj + jt * 16;
            *(float4*)&s_kv[j * 68 + ldq * 4] =
                *(const float4*)(Vbase + (size_t)(c * CK + j) * DD + ldq * 4);
        }
        __syncthreads();

        const int sbase = w * 16;
        #pragma unroll
        for (int jj = 0; jj < 16; jj++) {
            int j  = sbase + jj;
            int gj = c * CK + j;
            float4 v4 = *(const float4*)&s_kv[j * 68 + dkq * 4];
            #pragma unroll
            for (int r = 0; r < 4; r++) {
                float pv = s_sc[(rg * 4 + r) * 1024 + gj];
                acc4[r].x += pv * v4.x;
                acc4[r].y += pv * v4.y;
                acc4[r].z += pv * v4.z;
                acc4[r].w += pv * v4.w;
            }
        }
        __syncthreads();
    }

    #pragma unroll
    for (int r = 0; r < 4; r++)
        *(float4*)&s_part[((w * 8) + rg * 4 + r) * 64 + dkq * 4] = acc4[r];
    __syncthreads();

    // reduce 8 partials, scale, write out
    float* Obase = g_bufO[st] + ((size_t)(b * SS + q0)) * DD + h * DKK;
    #pragma unroll
    for (int rr = 0; rr < 2; rr++) {
        int e = tid + rr * 256;          // 0..511
        int r = e >> 6, d = e & 63;
        float s = 0.f;
        #pragma unroll
        for (int s8 = 0; s8 < 8; s8++) s += s_part[((s8 * 8) + r) * 64 + d];
        Obase[(size_t)r * DD + d] = s * s_rsum[r];
    }
}

// ---------------- launch ----------------
extern "C" void kernel_launch(void* const* d_in, const int* in_sizes, int n_in,
                              void* d_out, int out_size) {
    const float* q_m  = (const float*)d_in[0];
    const float* q_c  = (const float*)d_in[1];
    const float* k_m  = (const float*)d_in[2];
    const float* k_c  = (const float*)d_in[3];
    const float* v_m  = (const float*)d_in[4];
    const float* v_c  = (const float*)d_in[5];
    const float* Wk_m = (const float*)d_in[6];
    const float* bk_m = (const float*)d_in[7];
    const float* Wk_c = (const float*)d_in[8];
    const float* bk_c = (const float*)d_in[9];
    const float* Wv_m = (const float*)d_in[10];
    const float* bv_m = (const float*)d_in[11];
    const float* Wv_c = (const float*)d_in[12];
    const float* bv_c = (const float*)d_in[13];
    const float* Wo_m = (const float*)d_in[14];
    const float* bo_m = (const float*)d_in[15];
    const float* Wo_c = (const float*)d_in[16];
    const float* bo_c = (const float*)d_in[17];
    const float* gam  = (const float*)d_in[18];
    float* out = (float*)d_out;

    float *bQ, *bK, *bV, *bO;
    cudaGetSymbolAddress((void**)&bQ, g_bufQ);
    cudaGetSymbolAddress((void**)&bK, g_bufK);
    cudaGetSymbolAddress((void**)&bV, g_bufV);
    cudaGetSymbolAddress((void**)&bO, g_bufO);

    static bool attr_set = false;
    if (!attr_set) {
        cudaFuncSetAttribute(attn_kernel, cudaFuncAttributeMaxDynamicSharedMemorySize,
                             SMEM_ATTN_FLOATS * 4);
        attr_set = true;
    }

    // 6 projection GEMMs in one launch (Q and K share Wk per stream)
    GB8 proj{};
    proj.g[0] = { q_m, Wk_m, bk_m, bQ };
    proj.g[1] = { k_m, Wk_m, bk_m, bK };
    proj.g[2] = { v_m, Wv_m, bv_m, bV };
    proj.g[3] = { q_c, Wk_c, bk_c, bQ + BSD };
    proj.g[4] = { k_c, Wk_c, bk_c, bK + BSD };
    proj.g[5] = { v_c, Wv_c, bv_c, bV + BSD };
    gemm_batch_kernel<<<dim3(512 / GN, 4096 / GM, 6), 256>>>(proj);

    // attention (both streams)
    attn_kernel<<<dim3(SS / TQ, BB * HH, 2), 256, SMEM_ATTN_FLOATS * 4>>>(gam);

    // 2 output GEMMs in one launch
    GB8 outp{};
    outp.g[0] = { bO,       Wo_m, bo_m, out };
    outp.g[1] = { bO + BSD, Wo_c, bo_c, out + BSD };
    gemm_batch_kernel<<<dim3(512 / GN, 4096 / GM, 2), 256>>>(outp);
}